// round 1
// baseline (speedup 1.0000x reference)
#include <cuda_runtime.h>
#include <math.h>

#define N_IMG 128
#define N_REG 36
#define N_CAP 128
#define N_WORD 32
#define DIM 1024
#define LAMBDA_S 20.0f
#define EPSV 1e-8f

#define M_TOT (N_CAP * N_WORD)   // 4096
#define N_TOT (N_IMG * N_REG)    // 4608

// Scratch (static device globals; allocation-free)
__device__ float g_sim[(size_t)M_TOT * N_TOT];       // sim[m][n], m=c*32+w, n=i*36+r
__device__ float g_G[N_IMG * N_REG * N_REG];         // image Grams
__device__ float g_H[N_CAP * N_WORD * N_WORD];       // caption Grams
__device__ float g_imn[N_IMG * N_REG];               // image region norms
__device__ float g_cpn[N_CAP * N_WORD];              // caption word norms

// ---------------------------------------------------------------------------
// Kernel 1: per-image and per-caption Gram matrices + vector norms
// blocks 0..127 -> images, 128..255 -> captions. 256 threads.
// ---------------------------------------------------------------------------
__global__ void __launch_bounds__(256) gram_kernel(const float* __restrict__ images,
                                                   const float* __restrict__ captions) {
    __shared__ float chunk[N_REG * 64];  // 2304 floats (covers caption case too)
    int b = blockIdx.x;
    int t = threadIdx.x;

    if (b < N_IMG) {
        const float* base = images + (size_t)b * N_REG * DIM;
        float acc[6];
#pragma unroll
        for (int j = 0; j < 6; j++) acc[j] = 0.0f;
        for (int dc = 0; dc < DIM; dc += 64) {
            __syncthreads();
            for (int e = t; e < N_REG * 64; e += 256) {
                int r = e >> 6, x = e & 63;
                chunk[e] = base[(size_t)r * DIM + dc + x];
            }
            __syncthreads();
#pragma unroll
            for (int j = 0; j < 6; j++) {
                int p = t + j * 256;
                if (p < N_REG * N_REG) {
                    int r1 = p / N_REG, r2 = p - r1 * N_REG;
                    const float* c1 = &chunk[r1 * 64];
                    const float* c2 = &chunk[r2 * 64];
                    float s = acc[j];
#pragma unroll
                    for (int x = 0; x < 64; x++) s += c1[x] * c2[x];
                    acc[j] = s;
                }
            }
        }
#pragma unroll
        for (int j = 0; j < 6; j++) {
            int p = t + j * 256;
            if (p < N_REG * N_REG) {
                g_G[b * N_REG * N_REG + p] = acc[j];
                if ((p % (N_REG + 1)) == 0)  // diagonal: p = r*37
                    g_imn[b * N_REG + p / (N_REG + 1)] = sqrtf(acc[j]);
            }
        }
    } else {
        int cb = b - N_IMG;
        const float* base = captions + (size_t)cb * N_WORD * DIM;
        float acc[4];
#pragma unroll
        for (int j = 0; j < 4; j++) acc[j] = 0.0f;
        for (int dc = 0; dc < DIM; dc += 64) {
            __syncthreads();
            for (int e = t; e < N_WORD * 64; e += 256) {
                int r = e >> 6, x = e & 63;
                chunk[e] = base[(size_t)r * DIM + dc + x];
            }
            __syncthreads();
#pragma unroll
            for (int j = 0; j < 4; j++) {
                int p = t + j * 256;
                if (p < N_WORD * N_WORD) {
                    int w1 = p >> 5, w2 = p & 31;
                    const float* c1 = &chunk[w1 * 64];
                    const float* c2 = &chunk[w2 * 64];
                    float s = acc[j];
#pragma unroll
                    for (int x = 0; x < 64; x++) s += c1[x] * c2[x];
                    acc[j] = s;
                }
            }
        }
#pragma unroll
        for (int j = 0; j < 4; j++) {
            int p = t + j * 256;
            if (p < N_WORD * N_WORD) {
                g_H[cb * N_WORD * N_WORD + p] = acc[j];
                if ((p % (N_WORD + 1)) == 0)  // diagonal: p = w*33
                    g_cpn[cb * N_WORD + p / (N_WORD + 1)] = sqrtf(acc[j]);
            }
        }
    }
}

// ---------------------------------------------------------------------------
// Kernel 2: sim = captions(4096xK) @ images(4608xK)^T, fp32 NT GEMM
// 128x128 block tile, BK=16, 256 threads, 8x8 per thread.
// ---------------------------------------------------------------------------
#define BM 128
#define BN 128
#define BK 16
__global__ void __launch_bounds__(256) gemm_nt(const float* __restrict__ A,
                                               const float* __restrict__ B) {
    __shared__ float As[BK][BM];
    __shared__ float Bs[BK][BN];
    const int K = DIM;
    int tid = threadIdx.x;
    int bm = blockIdx.y * BM;
    int bn = blockIdx.x * BN;
    int ty = tid >> 4, tx = tid & 15;

    float acc[8][8];
#pragma unroll
    for (int i = 0; i < 8; i++)
#pragma unroll
        for (int j = 0; j < 8; j++) acc[i][j] = 0.0f;

    const float* Ag = A + (size_t)bm * K;
    const float* Bg = B + (size_t)bn * K;

    for (int k0 = 0; k0 < K; k0 += BK) {
#pragma unroll
        for (int l = 0; l < 2; l++) {
            int idx = tid + l * 256;          // 0..511
            int row = idx >> 2;
            int c4 = (idx & 3) << 2;
            float4 va = *(const float4*)&Ag[(size_t)row * K + k0 + c4];
            As[c4 + 0][row] = va.x; As[c4 + 1][row] = va.y;
            As[c4 + 2][row] = va.z; As[c4 + 3][row] = va.w;
            float4 vb = *(const float4*)&Bg[(size_t)row * K + k0 + c4];
            Bs[c4 + 0][row] = vb.x; Bs[c4 + 1][row] = vb.y;
            Bs[c4 + 2][row] = vb.z; Bs[c4 + 3][row] = vb.w;
        }
        __syncthreads();
#pragma unroll
        for (int kk = 0; kk < BK; kk++) {
            float am[8], bm_[8];
            *(float4*)&am[0]  = *(float4*)&As[kk][ty * 8];
            *(float4*)&am[4]  = *(float4*)&As[kk][ty * 8 + 4];
            *(float4*)&bm_[0] = *(float4*)&Bs[kk][tx * 8];
            *(float4*)&bm_[4] = *(float4*)&Bs[kk][tx * 8 + 4];
#pragma unroll
            for (int i = 0; i < 8; i++)
#pragma unroll
                for (int j = 0; j < 8; j++) acc[i][j] += am[i] * bm_[j];
        }
        __syncthreads();
    }
#pragma unroll
    for (int i = 0; i < 8; i++) {
        size_t row = bm + ty * 8 + i;
        float* Cp = g_sim + row * N_TOT + bn + tx * 8;
        *(float4*)Cp       = make_float4(acc[i][0], acc[i][1], acc[i][2], acc[i][3]);
        *(float4*)(Cp + 4) = make_float4(acc[i][4], acc[i][5], acc[i][6], acc[i][7]);
    }
}

// ---------------------------------------------------------------------------
// Kernel 3: fused focal attention for one (caption c, image i) pair per block.
// 128 threads. Uses Gram matrices for the weighted-context norms.
// ---------------------------------------------------------------------------
__global__ void __launch_bounds__(128) attn_kernel(float* __restrict__ out) {
    __shared__ float raw[N_REG][N_WORD];      // raw[r][w] = dot(img_r, cap_w)
    __shared__ float G[N_REG][N_REG];
    __shared__ float H[N_WORD][N_WORD];
    __shared__ float att[N_WORD][N_REG];      // t2i normalized (transposed)
    __shared__ float att2[N_REG][N_WORD];     // i2t normalized (transposed)
    __shared__ float imn[N_REG], cpn[N_WORD];
    __shared__ float red[N_WORD], red2[N_REG];

    int c = blockIdx.x, i = blockIdx.y, t = threadIdx.x;

    for (int e = t; e < N_REG * N_WORD; e += 128) {
        int w = e / N_REG, r = e - w * N_REG;
        raw[r][w] = g_sim[(size_t)(c * N_WORD + w) * N_TOT + i * N_REG + r];
    }
    for (int e = t; e < N_REG * N_REG; e += 128)
        G[e / N_REG][e % N_REG] = g_G[i * N_REG * N_REG + e];
    for (int e = t; e < N_WORD * N_WORD; e += 128)
        H[e >> 5][e & 31] = g_H[c * N_WORD * N_WORD + e];
    if (t < N_REG) imn[t] = g_imn[i * N_REG + t];
    if (t < N_WORD) cpn[t] = g_cpn[c * N_WORD + t];
    __syncthreads();

    // ======== t2i: context = regions (S=36), query = words (Q=32) ========
    // per-region leaky + l2norm over words, store transposed
    if (t < N_REG) {
        float v[N_WORD];
        float nrm = 0.0f;
#pragma unroll
        for (int w = 0; w < N_WORD; w++) {
            float x = raw[t][w];
            x = (x >= 0.0f) ? x : 0.1f * x;
            v[w] = x; nrm += x * x;
        }
        nrm = sqrtf(nrm) + EPSV;
        float inv = 1.0f / nrm;
#pragma unroll
        for (int w = 0; w < N_WORD; w++) att[w][t] = v[w] * inv;
    }
    __syncthreads();

    if (t < N_WORD) {
        float a[N_REG];
        float mx = -1e30f;
#pragma unroll
        for (int r = 0; r < N_REG; r++) { a[r] = att[t][r]; mx = fmaxf(mx, a[r]); }
        float s = 0.0f;
#pragma unroll
        for (int r = 0; r < N_REG; r++) { a[r] = expf(LAMBDA_S * (a[r] - mx)); s += a[r]; }
        float inv = 1.0f / s;
        float sum1 = 0.0f;
#pragma unroll
        for (int r = 0; r < N_REG; r++) { a[r] *= inv; sum1 += a[r]; }
        float st = 0.0f;
#pragma unroll
        for (int r = 0; r < N_REG; r++) {
            float f = a[r] * (float)N_REG - sum1;
            a[r] = (f > 0.0f) ? a[r] : 0.0f;
            st += a[r];
        }
        float invst = 1.0f / st;
        float num = 0.0f;
#pragma unroll
        for (int r = 0; r < N_REG; r++) { a[r] *= invst; num += a[r] * raw[r][t]; }
        float q = 0.0f;
#pragma unroll
        for (int r = 0; r < N_REG; r++) {
            float ar = a[r];
            if (ar != 0.0f) {
                float in = 0.0f;
#pragma unroll
                for (int r2 = 0; r2 < N_REG; r2++) in += G[r][r2] * a[r2];
                q += ar * in;
            }
        }
        float nb = fmaxf(sqrtf(fmaxf(q, 0.0f)), EPSV);
        float na = fmaxf(cpn[t], EPSV);
        red[t] = num / (na * nb);
    }

    // ======== i2t: context = words (S=32), query = regions (Q=36) ========
    if (t < N_WORD) {
        float v[N_REG];
        float nrm = 0.0f;
#pragma unroll
        for (int r = 0; r < N_REG; r++) {
            float x = raw[r][t];
            x = (x >= 0.0f) ? x : 0.1f * x;
            v[r] = x; nrm += x * x;
        }
        nrm = sqrtf(nrm) + EPSV;
        float inv = 1.0f / nrm;
#pragma unroll
        for (int r = 0; r < N_REG; r++) att2[r][t] = v[r] * inv;
    }
    __syncthreads();

    if (t < N_REG) {
        float a[N_WORD];
        float mx = -1e30f;
#pragma unroll
        for (int w = 0; w < N_WORD; w++) { a[w] = att2[t][w]; mx = fmaxf(mx, a[w]); }
        float s = 0.0f;
#pragma unroll
        for (int w = 0; w < N_WORD; w++) { a[w] = expf(LAMBDA_S * (a[w] - mx)); s += a[w]; }
        float inv = 1.0f / s;
        float sum1 = 0.0f;
#pragma unroll
        for (int w = 0; w < N_WORD; w++) { a[w] *= inv; sum1 += a[w]; }
        float st = 0.0f;
#pragma unroll
        for (int w = 0; w < N_WORD; w++) {
            float f = a[w] * (float)N_WORD - sum1;
            a[w] = (f > 0.0f) ? a[w] : 0.0f;
            st += a[w];
        }
        float invst = 1.0f / st;
        float num = 0.0f;
#pragma unroll
        for (int w = 0; w < N_WORD; w++) { a[w] *= invst; num += a[w] * raw[t][w]; }
        float q = 0.0f;
#pragma unroll
        for (int w = 0; w < N_WORD; w++) {
            float aw = a[w];
            if (aw != 0.0f) {
                float in = 0.0f;
#pragma unroll
                for (int w2 = 0; w2 < N_WORD; w2++) in += H[w][w2] * a[w2];
                q += aw * in;
            }
        }
        float nb = fmaxf(sqrtf(fmaxf(q, 0.0f)), EPSV);
        float na = fmaxf(imn[t], EPSV);
        red2[t] = num / (na * nb);
    }
    __syncthreads();

    if (t == 0) {
        float s1 = 0.0f;
#pragma unroll
        for (int w = 0; w < N_WORD; w++) s1 += red[w];
        float s2 = 0.0f;
#pragma unroll
        for (int r = 0; r < N_REG; r++) s2 += red2[r];
        out[i * N_CAP + c] = s1 / (float)N_WORD + s2 / (float)N_REG;
    }
}

// ---------------------------------------------------------------------------
extern "C" void kernel_launch(void* const* d_in, const int* in_sizes, int n_in,
                              void* d_out, int out_size) {
    const float* images = (const float*)d_in[0];
    const float* captions = (const float*)d_in[1];
    float* out = (float*)d_out;

    gram_kernel<<<256, 256>>>(images, captions);
    gemm_nt<<<dim3(N_TOT / BN, M_TOT / BM), 256>>>(captions, images);
    attn_kernel<<<dim3(N_CAP, N_IMG), 128>>>(out);
}

// round 3
// speedup vs baseline: 1.5977x; 1.5977x over previous
#include <cuda_runtime.h>
#include <cuda_bf16.h>
#include <math.h>
#include <stdint.h>

#define N_IMG 128
#define N_REG 36
#define N_CAP 128
#define N_WORD 32
#define DIM 1024
#define LAMBDA_S 20.0f
#define EPSV 1e-8f

#define M_TOT (N_CAP * N_WORD)   // 4096
#define N_TOT (N_IMG * N_REG)    // 4608

// ---------------- scratch (static device globals; allocation-free) ---------
__device__ float g_sim[(size_t)M_TOT * N_TOT];          // sim[m][n]
__device__ __nv_bfloat16 g_Ahi[(size_t)M_TOT * DIM];    // captions hi
__device__ __nv_bfloat16 g_Alo[(size_t)M_TOT * DIM];    // captions lo
__device__ __nv_bfloat16 g_Bhi[(size_t)N_TOT * DIM];    // images hi
__device__ __nv_bfloat16 g_Blo[(size_t)N_TOT * DIM];    // images lo
__device__ float g_G[N_IMG * N_REG * N_REG];            // image Grams
__device__ float g_H[N_CAP * N_WORD * N_WORD];          // caption Grams
__device__ float g_imn[N_IMG * N_REG];                  // image region norms
__device__ float g_cpn[N_CAP * N_WORD];                 // caption word norms

__device__ __forceinline__ uint32_t smem_u32(const void* p) {
    uint32_t a;
    asm("{ .reg .u64 t; cvta.to.shared.u64 t, %1; cvt.u32.u64 %0, t; }"
        : "=r"(a) : "l"(p));
    return a;
}

#define SWZ(x) ((x) ^ (((x) >> 3) & 0x70))

// ---------------------------------------------------------------------------
// Kernel 0: fp32 -> bf16 hi/lo split of captions and images
// ---------------------------------------------------------------------------
__global__ void __launch_bounds__(256) split_kernel(const float* __restrict__ images,
                                                    const float* __restrict__ captions) {
    const int capF4 = M_TOT * DIM / 4;
    const int imgF4 = N_TOT * DIM / 4;
    const int total = capF4 + imgF4;
    for (int idx = blockIdx.x * blockDim.x + threadIdx.x; idx < total;
         idx += gridDim.x * blockDim.x) {
        const float4* src;
        __nv_bfloat16 *hi, *lo;
        int o;
        if (idx < capF4) { src = (const float4*)captions; o = idx; hi = g_Ahi; lo = g_Alo; }
        else             { src = (const float4*)images;  o = idx - capF4; hi = g_Bhi; lo = g_Blo; }
        float4 v = src[o];
        float vv[4] = {v.x, v.y, v.z, v.w};
        __nv_bfloat16 h[4], l[4];
#pragma unroll
        for (int j = 0; j < 4; j++) {
            h[j] = __float2bfloat16(vv[j]);
            l[j] = __float2bfloat16(vv[j] - __bfloat162float(h[j]));
        }
        *(uint2*)(hi + 4 * (size_t)o) = *(uint2*)h;
        *(uint2*)(lo + 4 * (size_t)o) = *(uint2*)l;
    }
}

// ---------------------------------------------------------------------------
// Kernel 1: Gram matrices + norms. 3x3 register tile per thread, float4 k-vec.
// blocks 0..127 -> images (S=36), 128..255 -> captions (S=32).
// ---------------------------------------------------------------------------
__global__ void __launch_bounds__(256) gram_kernel(const float* __restrict__ images,
                                                   const float* __restrict__ captions) {
    __shared__ float4 sh[N_REG * 16];   // up to 36 rows x 64 floats
    int b = blockIdx.x, t = threadIdx.x;
    bool isImg = b < N_IMG;
    int S = isImg ? N_REG : N_WORD;
    const float* base = isImg ? images + (size_t)b * N_REG * DIM
                              : captions + (size_t)(b - N_IMG) * N_WORD * DIM;
    float* gout = isImg ? g_G + b * N_REG * N_REG : g_H + (b - N_IMG) * N_WORD * N_WORD;
    float* nout = isImg ? g_imn + b * N_REG : g_cpn + (b - N_IMG) * N_WORD;

    int ti = t / 12, tj = t % 12;       // 12x12 thread grid (t < 144 active)
    int r1b = ti * 3, r2b = tj * 3;
    float acc[3][3] = {{0.f,0.f,0.f},{0.f,0.f,0.f},{0.f,0.f,0.f}};

    for (int dc = 0; dc < DIM; dc += 64) {
        __syncthreads();
        for (int e = t; e < S * 16; e += 256) {
            int r = e >> 4, c = e & 15;
            sh[e] = *(const float4*)(base + (size_t)r * DIM + dc + c * 4);
        }
        __syncthreads();
        if (t < 144 && r1b < S && r2b < S) {
            int i0 = min(r1b + 0, S - 1) * 16, i1 = min(r1b + 1, S - 1) * 16,
                i2 = min(r1b + 2, S - 1) * 16;
            int j0 = min(r2b + 0, S - 1) * 16, j1 = min(r2b + 1, S - 1) * 16,
                j2 = min(r2b + 2, S - 1) * 16;
#pragma unroll 4
            for (int k = 0; k < 16; k++) {
                float4 a0 = sh[i0 + k], a1 = sh[i1 + k], a2 = sh[i2 + k];
                float4 c0 = sh[j0 + k], c1 = sh[j1 + k], c2 = sh[j2 + k];
#define DOT4(A, C) ((A).x * (C).x + (A).y * (C).y + (A).z * (C).z + (A).w * (C).w)
                acc[0][0] += DOT4(a0, c0); acc[0][1] += DOT4(a0, c1); acc[0][2] += DOT4(a0, c2);
                acc[1][0] += DOT4(a1, c0); acc[1][1] += DOT4(a1, c1); acc[1][2] += DOT4(a1, c2);
                acc[2][0] += DOT4(a2, c0); acc[2][1] += DOT4(a2, c1); acc[2][2] += DOT4(a2, c2);
#undef DOT4
            }
        }
    }
    if (t < 144) {
#pragma unroll
        for (int ii = 0; ii < 3; ii++)
#pragma unroll
            for (int jj = 0; jj < 3; jj++) {
                int r1 = r1b + ii, r2 = r2b + jj;
                if (r1 < S && r2 < S) {
                    gout[r1 * S + r2] = acc[ii][jj];
                    if (r1 == r2) nout[r1] = sqrtf(acc[ii][jj]);
                }
            }
    }
}

// ---------------------------------------------------------------------------
// Kernel 2: warp-MMA bf16-split GEMM. sim = Ahi*Bhi^T + Ahi*Blo^T + Alo*Bhi^T
// 128x128 CTA tile, 8 warps x (64x32), KC=64 double-buffered, SW128 swizzle.
// ---------------------------------------------------------------------------
#define KC 64
#define TILE_B (128 * KC * 2)        // 16384 bytes per operand tile
#define STAGE_B (2 * TILE_B)         // A + B = 32768
#define GEMM_SMEM (2 * STAGE_B)      // double buffer = 65536
#define NCHUNK 48                    // 3 terms x 16 chunks

__device__ __forceinline__ void ldm_x4(uint32_t& r0, uint32_t& r1, uint32_t& r2,
                                       uint32_t& r3, uint32_t addr) {
    asm volatile("ldmatrix.sync.aligned.m8n8.x4.shared.b16 {%0,%1,%2,%3}, [%4];"
                 : "=r"(r0), "=r"(r1), "=r"(r2), "=r"(r3) : "r"(addr));
}

__device__ __forceinline__ void mma_16816(float* c, const uint32_t* a, uint32_t b0,
                                          uint32_t b1) {
    asm volatile(
        "mma.sync.aligned.m16n8k16.row.col.f32.bf16.bf16.f32 "
        "{%0,%1,%2,%3}, {%4,%5,%6,%7}, {%8,%9}, {%0,%1,%2,%3};"
        : "+f"(c[0]), "+f"(c[1]), "+f"(c[2]), "+f"(c[3])
        : "r"(a[0]), "r"(a[1]), "r"(a[2]), "r"(a[3]), "r"(b0), "r"(b1));
}

__global__ void __launch_bounds__(256, 1) gemm_mma() {
    extern __shared__ char smem[];
    uint32_t sb = smem_u32(smem);
    int tid = threadIdx.x, wid = tid >> 5, lane = tid & 31;
    int bn = blockIdx.x * 128;   // image (N) tile
    int bm = blockIdx.y * 128;   // caption (M) tile
    int wm = (wid >> 2) * 64;    // warp m offset: 0 or 64
    int wn = (wid & 3) * 32;     // warp n offset: 0,32,64,96

    // per-term source pointers
    const __nv_bfloat16* Aterm[3] = {g_Ahi + (size_t)bm * DIM, g_Ahi + (size_t)bm * DIM,
                                     g_Alo + (size_t)bm * DIM};
    const __nv_bfloat16* Bterm[3] = {g_Bhi + (size_t)bn * DIM, g_Blo + (size_t)bn * DIM,
                                     g_Bhi + (size_t)bn * DIM};

    float acc[4][4][4];
#pragma unroll
    for (int i = 0; i < 4; i++)
#pragma unroll
        for (int j = 0; j < 4; j++)
#pragma unroll
            for (int k = 0; k < 4; k++) acc[i][j][k] = 0.0f;

    // ldmatrix per-lane addressing components
    int lr = lane & 7, sel = lane >> 3;
    int a_row = lr + ((sel & 1) << 3);        // +8 for sel 1,3
    int a_byte = (sel & 2) << 3;              // +16 for sel 2,3
    int b_row = lr + ((sel & 2) << 2);        // +8 for sel 2,3
    int b_byte = (sel & 1) << 4;              // +16 for sel 1,3

    // gmem load positions (8 x uint4 per thread per chunk: 4 A, 4 B)
    int g_row = tid >> 3;        // 0..31 base; +32*i
    int g_c16 = tid & 7;

    uint4 pa[4], pb[4];
    int ldrows[4], sts_off[4];
#pragma unroll
    for (int i = 0; i < 4; i++) {
        ldrows[i] = g_row + i * 32;
        sts_off[i] = SWZ(ldrows[i] * 128 + g_c16 * 16);
    }

#define LOAD_CHUNK(ch)                                                          \
    {                                                                           \
        int term = (ch) >> 4, kc = (ch) & 15;                                   \
        const __nv_bfloat16* As = Aterm[term] + kc * KC;                        \
        const __nv_bfloat16* Bs = Bterm[term] + kc * KC;                        \
        _Pragma("unroll") for (int i = 0; i < 4; i++) {                         \
            pa[i] = ((const uint4*)(As + (size_t)ldrows[i] * DIM))[g_c16];      \
            pb[i] = ((const uint4*)(Bs + (size_t)ldrows[i] * DIM))[g_c16];      \
        }                                                                       \
    }

#define STORE_CHUNK(s)                                                          \
    {                                                                           \
        char* st = smem + (s) * STAGE_B;                                        \
        _Pragma("unroll") for (int i = 0; i < 4; i++) {                         \
            *(uint4*)(st + sts_off[i]) = pa[i];                                 \
            *(uint4*)(st + TILE_B + sts_off[i]) = pb[i];                        \
        }                                                                       \
    }

    LOAD_CHUNK(0);
    STORE_CHUNK(0);
    __syncthreads();

    for (int ch = 0; ch < NCHUNK; ch++) {
        int s = ch & 1;
        if (ch + 1 < NCHUNK) LOAD_CHUNK(ch + 1);

        uint32_t sa = sb + s * STAGE_B;
        uint32_t sB = sa + TILE_B;
#pragma unroll
        for (int ks = 0; ks < 4; ks++) {
            uint32_t a[4][4], bb[2][4];
#pragma unroll
            for (int mf = 0; mf < 4; mf++) {
                uint32_t addr = sa + SWZ((wm + mf * 16 + a_row) * 128 + ks * 32 + a_byte);
                ldm_x4(a[mf][0], a[mf][1], a[mf][2], a[mf][3], addr);
            }
#pragma unroll
            for (int nh = 0; nh < 2; nh++) {
                uint32_t addr = sB + SWZ((wn + nh * 16 + b_row) * 128 + ks * 32 + b_byte);
                ldm_x4(bb[nh][0], bb[nh][1], bb[nh][2], bb[nh][3], addr);
            }
#pragma unroll
            for (int mf = 0; mf < 4; mf++)
#pragma unroll
                for (int nf = 0; nf < 4; nf++)
                    mma_16816(acc[mf][nf], a[mf], bb[nf >> 1][(nf & 1) * 2],
                              bb[nf >> 1][(nf & 1) * 2 + 1]);
        }

        if (ch + 1 < NCHUNK) STORE_CHUNK(s ^ 1);
        __syncthreads();
    }

    // epilogue: write 64x32 warp tile
    int g = lane >> 2, t4 = lane & 3;
#pragma unroll
    for (int mf = 0; mf < 4; mf++) {
#pragma unroll
        for (int nf = 0; nf < 4; nf++) {
            int row0 = bm + wm + mf * 16 + g;
            int col = bn + wn + nf * 8 + 2 * t4;
            float* p0 = g_sim + (size_t)row0 * N_TOT + col;
            float* p1 = p0 + 8 * N_TOT;
            *(float2*)p0 = make_float2(acc[mf][nf][0], acc[mf][nf][1]);
            *(float2*)p1 = make_float2(acc[mf][nf][2], acc[mf][nf][3]);
        }
    }
}

// ---------------------------------------------------------------------------
// Kernel 3: fused focal attention, one (caption c, image i) pair per block.
// ---------------------------------------------------------------------------
__global__ void __launch_bounds__(128) attn_kernel(float* __restrict__ out) {
    __shared__ float raw[N_REG][N_WORD];
    __shared__ float G[N_REG][N_REG];
    __shared__ float H[N_WORD][N_WORD];
    __shared__ float att[N_WORD][N_REG];
    __shared__ float att2[N_REG][N_WORD];
    __shared__ float imn[N_REG], cpn[N_WORD];
    __shared__ float red[N_WORD], red2[N_REG];

    int c = blockIdx.x, i = blockIdx.y, t = threadIdx.x;

    for (int e = t; e < N_REG * N_WORD; e += 128) {
        int w = e / N_REG, r = e - w * N_REG;
        raw[r][w] = g_sim[(size_t)(c * N_WORD + w) * N_TOT + i * N_REG + r];
    }
    for (int e = t; e < N_REG * N_REG; e += 128)
        G[e / N_REG][e % N_REG] = g_G[i * N_REG * N_REG + e];
    for (int e = t; e < N_WORD * N_WORD; e += 128)
        H[e >> 5][e & 31] = g_H[c * N_WORD * N_WORD + e];
    if (t < N_REG) imn[t] = g_imn[i * N_REG + t];
    if (t < N_WORD) cpn[t] = g_cpn[c * N_WORD + t];
    __syncthreads();

    // t2i: per-region leaky + l2norm over words
    if (t < N_REG) {
        float v[N_WORD];
        float nrm = 0.0f;
#pragma unroll
        for (int w = 0; w < N_WORD; w++) {
            float x = raw[t][w];
            x = (x >= 0.0f) ? x : 0.1f * x;
            v[w] = x; nrm += x * x;
        }
        float inv = 1.0f / (sqrtf(nrm) + EPSV);
#pragma unroll
        for (int w = 0; w < N_WORD; w++) att[w][t] = v[w] * inv;
    }
    __syncthreads();

    if (t < N_WORD) {
        float a[N_REG];
        float mx = -1e30f;
#pragma unroll
        for (int r = 0; r < N_REG; r++) { a[r] = att[t][r]; mx = fmaxf(mx, a[r]); }
        float s = 0.0f;
#pragma unroll
        for (int r = 0; r < N_REG; r++) { a[r] = expf(LAMBDA_S * (a[r] - mx)); s += a[r]; }
        float inv = 1.0f / s;
        float sum1 = 0.0f;
#pragma unroll
        for (int r = 0; r < N_REG; r++) { a[r] *= inv; sum1 += a[r]; }
        float st = 0.0f;
#pragma unroll
        for (int r = 0; r < N_REG; r++) {
            float f = a[r] * (float)N_REG - sum1;
            a[r] = (f > 0.0f) ? a[r] : 0.0f;
            st += a[r];
        }
        float invst = 1.0f / st;
        float num = 0.0f;
#pragma unroll
        for (int r = 0; r < N_REG; r++) { a[r] *= invst; num += a[r] * raw[r][t]; }
        float q = 0.0f;
#pragma unroll
        for (int r = 0; r < N_REG; r++) {
            float ar = a[r];
            if (ar != 0.0f) {
                float in = 0.0f;
#pragma unroll
                for (int r2 = 0; r2 < N_REG; r2++) in += G[r][r2] * a[r2];
                q += ar * in;
            }
        }
        float nb = fmaxf(sqrtf(fmaxf(q, 0.0f)), EPSV);
        float na = fmaxf(cpn[t], EPSV);
        red[t] = num / (na * nb);
    }

    // i2t: per-word leaky + l2norm over regions
    if (t < N_WORD) {
        float v[N_REG];
        float nrm = 0.0f;
#pragma unroll
        for (int r = 0; r < N_REG; r++) {
            float x = raw[r][t];
            x = (x >= 0.0f) ? x : 0.1f * x;
            v[r] = x; nrm += x * x;
        }
        float inv = 1.0f / (sqrtf(nrm) + EPSV);
#pragma unroll
        for (int r = 0; r < N_REG; r++) att2[r][t] = v[r] * inv;
    }
    __syncthreads();

    if (t < N_REG) {
        float a[N_WORD];
        float mx = -1e30f;
#pragma unroll
        for (int w = 0; w < N_WORD; w++) { a[w] = att2[t][w]; mx = fmaxf(mx, a[w]); }
        float s = 0.0f;
#pragma unroll
        for (int w = 0; w < N_WORD; w++) { a[w] = expf(LAMBDA_S * (a[w] - mx)); s += a[w]; }
        float inv = 1.0f / s;
        float sum1 = 0.0f;
#pragma unroll
        for (int w = 0; w < N_WORD; w++) { a[w] *= inv; sum1 += a[w]; }
        float st = 0.0f;
#pragma unroll
        for (int w = 0; w < N_WORD; w++) {
            float f = a[w] * (float)N_WORD - sum1;
            a[w] = (f > 0.0f) ? a[w] : 0.0f;
            st += a[w];
        }
        float invst = 1.0f / st;
        float num = 0.0f;
#pragma unroll
        for (int w = 0; w < N_WORD; w++) { a[w] *= invst; num += a[w] * raw[t][w]; }
        float q = 0.0f;
#pragma unroll
        for (int w = 0; w < N_WORD; w++) {
            float aw = a[w];
            if (aw != 0.0f) {
                float in = 0.0f;
#pragma unroll
                for (int w2 = 0; w2 < N_WORD; w2++) in += H[w][w2] * a[w2];
                q += aw * in;
            }
        }
        float nb = fmaxf(sqrtf(fmaxf(q, 0.0f)), EPSV);
        float na = fmaxf(imn[t], EPSV);
        red2[t] = num / (na * nb);
    }
    __syncthreads();

    if (t == 0) {
        float s1 = 0.0f;
#pragma unroll
        for (int w = 0; w < N_WORD; w++) s1 += red[w];
        float s2 = 0.0f;
#pragma unroll
        for (int r = 0; r < N_REG; r++) s2 += red2[r];
        out[i * N_CAP + c] = s1 / (float)N_WORD + s2 / (float)N_REG;
    }
}

// ---------------------------------------------------------------------------
extern "C" void kernel_launch(void* const* d_in, const int* in_sizes, int n_in,
                              void* d_out, int out_size) {
    const float* images = (const float*)d_in[0];
    const float* captions = (const float*)d_in[1];
    float* out = (float*)d_out;

    static int smem_set = 0;
    if (!smem_set) {
        cudaFuncSetAttribute(gemm_mma, cudaFuncAttributeMaxDynamicSharedMemorySize,
                             GEMM_SMEM);
        smem_set = 1;
    }

    split_kernel<<<2048, 256>>>(images, captions);
    gram_kernel<<<256, 256>>>(images, captions);
    gemm_mma<<<dim3(N_TOT / 128, M_TOT / 128), 256, GEMM_SMEM>>>();
    attn_kernel<<<dim3(N_CAP, N_IMG), 128>>>(out);
}

// round 4
// speedup vs baseline: 2.4446x; 1.5301x over previous
#include <cuda_runtime.h>
#include <cuda_bf16.h>
#include <math.h>
#include <stdint.h>

#define N_IMG 128
#define N_REG 36
#define N_CAP 128
#define N_WORD 32
#define DIM 1024
#define LAMBDA_S 20.0f
#define EPSV 1e-8f

#define M_TOT (N_CAP * N_WORD)   // 4096
#define N_TOT (N_IMG * N_REG)    // 4608

// ---------------- scratch (static device globals; allocation-free) ---------
__device__ float g_sim[(size_t)M_TOT * N_TOT];          // sim[m][n]
__device__ __nv_bfloat16 g_Ahi[(size_t)M_TOT * DIM];    // captions hi
__device__ __nv_bfloat16 g_Alo[(size_t)M_TOT * DIM];    // captions lo
__device__ __nv_bfloat16 g_Bhi[(size_t)N_TOT * DIM];    // images hi
__device__ __nv_bfloat16 g_Blo[(size_t)N_TOT * DIM];    // images lo
__device__ float g_G[N_IMG * N_REG * N_REG];            // image Grams
__device__ float g_H[N_CAP * N_WORD * N_WORD];          // caption Grams
__device__ float g_imn[N_IMG * N_REG];                  // image region norms
__device__ float g_cpn[N_CAP * N_WORD];                 // caption word norms

__device__ __forceinline__ uint32_t smem_u32(const void* p) {
    uint32_t a;
    asm("{ .reg .u64 t; cvta.to.shared.u64 t, %1; cvt.u32.u64 %0, t; }"
        : "=r"(a) : "l"(p));
    return a;
}

#define SWZ(x) ((x) ^ (((x) >> 3) & 0x70))

// ---------------------------------------------------------------------------
// Kernel 0: fp32 -> bf16 hi/lo split of captions and images
// ---------------------------------------------------------------------------
__global__ void __launch_bounds__(256) split_kernel(const float* __restrict__ images,
                                                    const float* __restrict__ captions) {
    const int capF4 = M_TOT * DIM / 4;
    const int imgF4 = N_TOT * DIM / 4;
    const int total = capF4 + imgF4;
    for (int idx = blockIdx.x * blockDim.x + threadIdx.x; idx < total;
         idx += gridDim.x * blockDim.x) {
        const float4* src;
        __nv_bfloat16 *hi, *lo;
        int o;
        if (idx < capF4) { src = (const float4*)captions; o = idx; hi = g_Ahi; lo = g_Alo; }
        else             { src = (const float4*)images;  o = idx - capF4; hi = g_Bhi; lo = g_Blo; }
        float4 v = src[o];
        float vv[4] = {v.x, v.y, v.z, v.w};
        __nv_bfloat16 h[4], l[4];
#pragma unroll
        for (int j = 0; j < 4; j++) {
            h[j] = __float2bfloat16(vv[j]);
            l[j] = __float2bfloat16(vv[j] - __bfloat162float(h[j]));
        }
        *(uint2*)(hi + 4 * (size_t)o) = *(uint2*)h;
        *(uint2*)(lo + 4 * (size_t)o) = *(uint2*)l;
    }
}

// ---------------------------------------------------------------------------
// Kernel 1: Gram matrices + norms. 3x3 register tile per thread, float4 k-vec.
// ---------------------------------------------------------------------------
__global__ void __launch_bounds__(256) gram_kernel(const float* __restrict__ images,
                                                   const float* __restrict__ captions) {
    __shared__ float4 sh[N_REG * 16];
    int b = blockIdx.x, t = threadIdx.x;
    bool isImg = b < N_IMG;
    int S = isImg ? N_REG : N_WORD;
    const float* base = isImg ? images + (size_t)b * N_REG * DIM
                              : captions + (size_t)(b - N_IMG) * N_WORD * DIM;
    float* gout = isImg ? g_G + b * N_REG * N_REG : g_H + (b - N_IMG) * N_WORD * N_WORD;
    float* nout = isImg ? g_imn + b * N_REG : g_cpn + (b - N_IMG) * N_WORD;

    int ti = t / 12, tj = t % 12;
    int r1b = ti * 3, r2b = tj * 3;
    float acc[3][3] = {{0.f,0.f,0.f},{0.f,0.f,0.f},{0.f,0.f,0.f}};

    for (int dc = 0; dc < DIM; dc += 64) {
        __syncthreads();
        for (int e = t; e < S * 16; e += 256) {
            int r = e >> 4, c = e & 15;
            sh[e] = *(const float4*)(base + (size_t)r * DIM + dc + c * 4);
        }
        __syncthreads();
        if (t < 144 && r1b < S && r2b < S) {
            int i0 = min(r1b + 0, S - 1) * 16, i1 = min(r1b + 1, S - 1) * 16,
                i2 = min(r1b + 2, S - 1) * 16;
            int j0 = min(r2b + 0, S - 1) * 16, j1 = min(r2b + 1, S - 1) * 16,
                j2 = min(r2b + 2, S - 1) * 16;
#pragma unroll 4
            for (int k = 0; k < 16; k++) {
                float4 a0 = sh[i0 + k], a1 = sh[i1 + k], a2 = sh[i2 + k];
                float4 c0 = sh[j0 + k], c1 = sh[j1 + k], c2 = sh[j2 + k];
#define DOT4(A, C) ((A).x * (C).x + (A).y * (C).y + (A).z * (C).z + (A).w * (C).w)
                acc[0][0] += DOT4(a0, c0); acc[0][1] += DOT4(a0, c1); acc[0][2] += DOT4(a0, c2);
                acc[1][0] += DOT4(a1, c0); acc[1][1] += DOT4(a1, c1); acc[1][2] += DOT4(a1, c2);
                acc[2][0] += DOT4(a2, c0); acc[2][1] += DOT4(a2, c1); acc[2][2] += DOT4(a2, c2);
#undef DOT4
            }
        }
    }
    if (t < 144) {
#pragma unroll
        for (int ii = 0; ii < 3; ii++)
#pragma unroll
            for (int jj = 0; jj < 3; jj++) {
                int r1 = r1b + ii, r2 = r2b + jj;
                if (r1 < S && r2 < S) {
                    gout[r1 * S + r2] = acc[ii][jj];
                    if (r1 == r2) nout[r1] = sqrtf(acc[ii][jj]);
                }
            }
    }
}

// ---------------------------------------------------------------------------
// Kernel 2: warp-MMA bf16-split GEMM with cp.async double buffering.
// ---------------------------------------------------------------------------
#define KC 64
#define TILE_B (128 * KC * 2)        // 16384 bytes per operand tile
#define STAGE_B (2 * TILE_B)         // 32768
#define GEMM_SMEM (2 * STAGE_B)      // 65536
#define NCHUNK 48                    // 3 terms x 16 chunks

__device__ __forceinline__ void ldm_x4(uint32_t& r0, uint32_t& r1, uint32_t& r2,
                                       uint32_t& r3, uint32_t addr) {
    asm volatile("ldmatrix.sync.aligned.m8n8.x4.shared.b16 {%0,%1,%2,%3}, [%4];"
                 : "=r"(r0), "=r"(r1), "=r"(r2), "=r"(r3) : "r"(addr));
}

__device__ __forceinline__ void mma_16816(float* c, const uint32_t* a, uint32_t b0,
                                          uint32_t b1) {
    asm volatile(
        "mma.sync.aligned.m16n8k16.row.col.f32.bf16.bf16.f32 "
        "{%0,%1,%2,%3}, {%4,%5,%6,%7}, {%8,%9}, {%0,%1,%2,%3};"
        : "+f"(c[0]), "+f"(c[1]), "+f"(c[2]), "+f"(c[3])
        : "r"(a[0]), "r"(a[1]), "r"(a[2]), "r"(a[3]), "r"(b0), "r"(b1));
}

__device__ __forceinline__ void cp16(uint32_t dst, const void* src) {
    asm volatile("cp.async.cg.shared.global [%0], [%1], 16;" :: "r"(dst), "l"(src));
}

__global__ void __launch_bounds__(256, 2) gemm_mma() {
    extern __shared__ char smem[];
    uint32_t sb = smem_u32(smem);
    int tid = threadIdx.x, wid = tid >> 5, lane = tid & 31;
    int bn = blockIdx.x * 128;
    int bm = blockIdx.y * 128;
    int wm = (wid >> 2) * 64;
    int wn = (wid & 3) * 32;

    const __nv_bfloat16* Aterm[3] = {g_Ahi + (size_t)bm * DIM, g_Ahi + (size_t)bm * DIM,
                                     g_Alo + (size_t)bm * DIM};
    const __nv_bfloat16* Bterm[3] = {g_Bhi + (size_t)bn * DIM, g_Blo + (size_t)bn * DIM,
                                     g_Bhi + (size_t)bn * DIM};

    float acc[4][4][4];
#pragma unroll
    for (int i = 0; i < 4; i++)
#pragma unroll
        for (int j = 0; j < 4; j++)
#pragma unroll
            for (int k = 0; k < 4; k++) acc[i][j][k] = 0.0f;

    int lr = lane & 7, sel = lane >> 3;
    int a_row = lr + ((sel & 1) << 3);
    int a_byte = (sel & 2) << 3;
    int b_row = lr + ((sel & 2) << 2);
    int b_byte = (sel & 1) << 4;

    int g_row = tid >> 3;
    int g_c16 = tid & 7;
    int ldrows[4], sts_off[4];
#pragma unroll
    for (int i = 0; i < 4; i++) {
        ldrows[i] = g_row + i * 32;
        sts_off[i] = SWZ(ldrows[i] * 128 + g_c16 * 16);
    }

#define ISSUE_CHUNK(ch, s)                                                      \
    {                                                                           \
        int term = (ch) >> 4, kc = (ch) & 15;                                   \
        const __nv_bfloat16* As = Aterm[term] + kc * KC;                        \
        const __nv_bfloat16* Bs = Bterm[term] + kc * KC;                        \
        uint32_t st = sb + (s) * STAGE_B;                                       \
        _Pragma("unroll") for (int i = 0; i < 4; i++) {                         \
            cp16(st + sts_off[i], As + (size_t)ldrows[i] * DIM + g_c16 * 8);    \
            cp16(st + TILE_B + sts_off[i],                                      \
                 Bs + (size_t)ldrows[i] * DIM + g_c16 * 8);                     \
        }                                                                       \
        asm volatile("cp.async.commit_group;" ::: "memory");                    \
    }

    ISSUE_CHUNK(0, 0);

    for (int ch = 0; ch < NCHUNK; ch++) {
        int s = ch & 1;
        if (ch + 1 < NCHUNK) {
            ISSUE_CHUNK(ch + 1, s ^ 1);
            asm volatile("cp.async.wait_group 1;" ::: "memory");
        } else {
            asm volatile("cp.async.wait_group 0;" ::: "memory");
        }
        __syncthreads();

        uint32_t sa = sb + s * STAGE_B;
        uint32_t sB = sa + TILE_B;
#pragma unroll
        for (int ks = 0; ks < 4; ks++) {
            uint32_t a[4][4], bb[2][4];
#pragma unroll
            for (int mf = 0; mf < 4; mf++) {
                uint32_t addr = sa + SWZ((wm + mf * 16 + a_row) * 128 + ks * 32 + a_byte);
                ldm_x4(a[mf][0], a[mf][1], a[mf][2], a[mf][3], addr);
            }
#pragma unroll
            for (int nh = 0; nh < 2; nh++) {
                uint32_t addr = sB + SWZ((wn + nh * 16 + b_row) * 128 + ks * 32 + b_byte);
                ldm_x4(bb[nh][0], bb[nh][1], bb[nh][2], bb[nh][3], addr);
            }
#pragma unroll
            for (int mf = 0; mf < 4; mf++)
#pragma unroll
                for (int nf = 0; nf < 4; nf++)
                    mma_16816(acc[mf][nf], a[mf], bb[nf >> 1][(nf & 1) * 2],
                              bb[nf >> 1][(nf & 1) * 2 + 1]);
        }
        __syncthreads();
    }

    int g = lane >> 2, t4 = lane & 3;
#pragma unroll
    for (int mf = 0; mf < 4; mf++) {
#pragma unroll
        for (int nf = 0; nf < 4; nf++) {
            int row0 = bm + wm + mf * 16 + g;
            int col = bn + wn + nf * 8 + 2 * t4;
            float* p0 = g_sim + (size_t)row0 * N_TOT + col;
            float* p1 = p0 + 8 * N_TOT;
            *(float2*)p0 = make_float2(acc[mf][nf][0], acc[mf][nf][1]);
            *(float2*)p1 = make_float2(acc[mf][nf][2], acc[mf][nf][3]);
        }
    }
}

// ---------------------------------------------------------------------------
// Kernel 3: fused focal attention, one (c,i) pair per 128-thread block.
// Quad-of-4-threads per query; shfl reductions; register-cached attn vector.
// ---------------------------------------------------------------------------
__device__ __forceinline__ float qmax(float v, unsigned m) {
    v = fmaxf(v, __shfl_xor_sync(m, v, 1));
    v = fmaxf(v, __shfl_xor_sync(m, v, 2));
    return v;
}
__device__ __forceinline__ float qsum(float v, unsigned m) {
    v += __shfl_xor_sync(m, v, 1);
    v += __shfl_xor_sync(m, v, 2);
    return v;
}

__global__ void __launch_bounds__(128) attn_kernel(float* __restrict__ out) {
    __shared__ float raw[N_REG][N_WORD + 1];   // [r][w], padded
    __shared__ float G[N_REG][N_REG];          // 36x36, rows 144B (f4-aligned)
    __shared__ float Hs[N_WORD][36];           // padded rows
    __shared__ float A1[N_WORD][36];           // t2i attn [w][r]
    __shared__ float A2[N_REG][36];            // i2t attn [r][w]
    __shared__ float nrmi[N_REG], nrmw[N_WORD];
    __shared__ float imn[N_REG], cpn[N_WORD];
    __shared__ float red[N_WORD], red2[N_REG];

    int c = blockIdx.x, i = blockIdx.y, t = threadIdx.x;

    for (int e = t; e < N_REG * N_WORD; e += 128) {
        int w = e / N_REG, r = e - w * N_REG;
        raw[r][w] = g_sim[(size_t)(c * N_WORD + w) * N_TOT + i * N_REG + r];
    }
    for (int e = t; e < N_REG * N_REG; e += 128)
        G[e / N_REG][e % N_REG] = g_G[i * N_REG * N_REG + e];
    for (int e = t; e < N_WORD * N_WORD; e += 128)
        Hs[e >> 5][e & 31] = g_H[c * N_WORD * N_WORD + e];
    if (t < N_REG) imn[t] = g_imn[i * N_REG + t];
    if (t < N_WORD) cpn[t] = g_cpn[c * N_WORD + t];
    __syncthreads();

    // norms: regions (t2i, per-region over words) and words (i2t, per-word over regions)
    if (t < N_REG) {
        float s = 0.0f;
#pragma unroll
        for (int w = 0; w < N_WORD; w++) {
            float x = raw[t][w];
            x = (x >= 0.0f) ? x : 0.1f * x;
            s += x * x;
        }
        nrmi[t] = 1.0f / (sqrtf(s) + EPSV);
    } else if (t >= 64 && t < 96) {
        int w = t - 64;
        float s = 0.0f;
#pragma unroll
        for (int r = 0; r < N_REG; r++) {
            float x = raw[r][w];
            x = (x >= 0.0f) ? x : 0.1f * x;
            s += x * x;
        }
        nrmw[w] = 1.0f / (sqrtf(s) + EPSV);
    }
    __syncthreads();

    // ===== t2i: 32 words, quad of 4 threads per word, 9 regions each =====
    {
        int w = t >> 2, j = t & 3;
        float a[9], rw[9];
        float mx = -1e30f;
#pragma unroll
        for (int k = 0; k < 9; k++) {
            int r = j + 4 * k;
            float x = raw[r][w];
            rw[k] = x;
            x = (x >= 0.0f) ? x : 0.1f * x;
            x *= nrmi[r];
            a[k] = x;
            mx = fmaxf(mx, x);
        }
        mx = qmax(mx, 0xFFFFFFFFu);
        float s = 0.0f;
#pragma unroll
        for (int k = 0; k < 9; k++) { a[k] = __expf(LAMBDA_S * (a[k] - mx)); s += a[k]; }
        s = qsum(s, 0xFFFFFFFFu);
        float inv = 1.0f / s;
        float sum1 = 0.0f;
#pragma unroll
        for (int k = 0; k < 9; k++) { a[k] *= inv; sum1 += a[k]; }
        sum1 = qsum(sum1, 0xFFFFFFFFu);
        float st = 0.0f;
#pragma unroll
        for (int k = 0; k < 9; k++) {
            a[k] = (a[k] * (float)N_REG - sum1 > 0.0f) ? a[k] : 0.0f;
            st += a[k];
        }
        st = qsum(st, 0xFFFFFFFFu);
        float invst = 1.0f / st;
        float num = 0.0f;
#pragma unroll
        for (int k = 0; k < 9; k++) { a[k] *= invst; num += a[k] * rw[k]; }
        num = qsum(num, 0xFFFFFFFFu);
#pragma unroll
        for (int k = 0; k < 9; k++) A1[w][j + 4 * k] = a[k];
        __syncwarp();
        float4 av[9];
#pragma unroll
        for (int k = 0; k < 9; k++) av[k] = *(const float4*)&A1[w][4 * k];
        float q = 0.0f;
#pragma unroll
        for (int k = 0; k < 9; k++) {
            if (a[k] != 0.0f) {
                int r = j + 4 * k;
                const float4* Gr = (const float4*)&G[r][0];
                float d = 0.0f;
#pragma unroll
                for (int c4 = 0; c4 < 9; c4++) {
                    float4 g = Gr[c4], v = av[c4];
                    d += g.x * v.x + g.y * v.y + g.z * v.z + g.w * v.w;
                }
                q += a[k] * d;
            }
        }
        q = qsum(q, 0xFFFFFFFFu);
        if (j == 0) {
            float nb = fmaxf(sqrtf(fmaxf(q, 0.0f)), EPSV);
            red[w] = num / (fmaxf(cpn[w], EPSV) * nb);
        }
    }
    __syncthreads();

    // ===== i2t: 36 regions, quad per region; batch A = regions 0..31 (all
    // threads), batch B = regions 32..35 (threads 0..15, mask 0xFFFF) =====
#define I2T_WORK(r, j, MASK)                                                    \
    {                                                                           \
        float a[8], rw[8];                                                      \
        float mx = -1e30f;                                                      \
        _Pragma("unroll") for (int k = 0; k < 8; k++) {                         \
            int w = (j) + 4 * k;                                                \
            float x = raw[r][w];                                                \
            rw[k] = x;                                                          \
            x = (x >= 0.0f) ? x : 0.1f * x;                                     \
            x *= nrmw[w];                                                       \
            a[k] = x;                                                           \
            mx = fmaxf(mx, x);                                                  \
        }                                                                       \
        mx = qmax(mx, MASK);                                                    \
        float s = 0.0f;                                                         \
        _Pragma("unroll") for (int k = 0; k < 8; k++) {                         \
            a[k] = __expf(LAMBDA_S * (a[k] - mx));                              \
            s += a[k];                                                          \
        }                                                                       \
        s = qsum(s, MASK);                                                      \
        float inv = 1.0f / s;                                                   \
        float sum1 = 0.0f;                                                      \
        _Pragma("unroll") for (int k = 0; k < 8; k++) {                         \
            a[k] *= inv;                                                        \
            sum1 += a[k];                                                       \
        }                                                                       \
        sum1 = qsum(sum1, MASK);                                                \
        float st = 0.0f;                                                        \
        _Pragma("unroll") for (int k = 0; k < 8; k++) {                         \
            a[k] = (a[k] * (float)N_WORD - sum1 > 0.0f) ? a[k] : 0.0f;          \
            st += a[k];                                                         \
        }                                                                       \
        st = qsum(st, MASK);                                                    \
        float invst = 1.0f / st;                                                \
        float num = 0.0f;                                                       \
        _Pragma("unroll") for (int k = 0; k < 8; k++) {                         \
            a[k] *= invst;                                                      \
            num += a[k] * rw[k];                                                \
        }                                                                       \
        num = qsum(num, MASK);                                                  \
        _Pragma("unroll") for (int k = 0; k < 8; k++) A2[r][(j) + 4 * k] = a[k];\
        __syncwarp(MASK);                                                       \
        float4 av[8];                                                           \
        _Pragma("unroll") for (int k = 0; k < 8; k++)                           \
            av[k] = *(const float4*)&A2[r][4 * k];                              \
        float q = 0.0f;                                                         \
        _Pragma("unroll") for (int k = 0; k < 8; k++) {                         \
            if (a[k] != 0.0f) {                                                 \
                int w = (j) + 4 * k;                                            \
                const float4* Hr = (const float4*)&Hs[w][0];                    \
                float d = 0.0f;                                                 \
                _Pragma("unroll") for (int c4 = 0; c4 < 8; c4++) {              \
                    float4 g = Hr[c4], v = av[c4];                              \
                    d += g.x * v.x + g.y * v.y + g.z * v.z + g.w * v.w;         \
                }                                                               \
                q += a[k] * d;                                                  \
            }                                                                   \
        }                                                                       \
        q = qsum(q, MASK);                                                      \
        if ((j) == 0) {                                                         \
            float nb = fmaxf(sqrtf(fmaxf(q, 0.0f)), EPSV);                      \
            red2[r] = num / (fmaxf(imn[r], EPSV) * nb);                         \
        }                                                                       \
    }

    {
        int r = t >> 2, j = t & 3;
        I2T_WORK(r, j, 0xFFFFFFFFu);
    }
    if (t < 16) {
        int r = 32 + (t >> 2), j = t & 3;
        I2T_WORK(r, j, 0xFFFFu);
    }
    __syncthreads();

    if (t == 0) {
        float s1 = 0.0f;
#pragma unroll
        for (int w = 0; w < N_WORD; w++) s1 += red[w];
        float s2 = 0.0f;
#pragma unroll
        for (int r = 0; r < N_REG; r++) s2 += red2[r];
        out[i * N_CAP + c] = s1 / (float)N_WORD + s2 / (float)N_REG;
    }
}

// ---------------------------------------------------------------------------
extern "C" void kernel_launch(void* const* d_in, const int* in_sizes, int n_in,
                              void* d_out, int out_size) {
    const float* images = (const float*)d_in[0];
    const float* captions = (const float*)d_in[1];
    float* out = (float*)d_out;

    cudaFuncSetAttribute(gemm_mma, cudaFuncAttributeMaxDynamicSharedMemorySize,
                         GEMM_SMEM);

    split_kernel<<<2048, 256>>>(images, captions);
    gram_kernel<<<256, 256>>>(images, captions);
    gemm_mma<<<dim3(N_TOT / 128, M_TOT / 128), 256, GEMM_SMEM>>>();
    attn_kernel<<<dim3(N_CAP, N_IMG), 128>>>(out);
}